// round 2
// baseline (speedup 1.0000x reference)
#include <cuda_runtime.h>
#include <math.h>

// ---------------------------------------------------------------------------
// m_btabl fused. R2: LDS-traffic reduction.
//  * 2 samples per thread: W1-row LDS amortized over two register-resident y2.
//  * GEMM1 x reads vectorized to LDS.128 (rows 2q,2q+1 are contiguous).
//  * cp.async double-issue staging of next x tile overlapped under GEMM2.
// ---------------------------------------------------------------------------

#define D1v 40
#define T1v 10
#define D2v 120
#define T2v 5
#define D3v 3

#define BLK 160      // 32 sample-slots x 5 t-columns; each thread does 2 samples
#define SPT 64       // samples per tile
#define TPB 4        // tiles per block -> 256 samples/block
#define XSTR 404     // padded x row stride (floats); 404 mod 32 = 20 -> conflict-free

// smem layout (float offsets)
#define SW1   0                      // 4800  scaled BL_W1 [120][40]
#define SBo   4800                   // 600   BL_B [120][5]
#define STW   5400                   // 480   scaled T_W1 transposed+padded [120][4]
#define SW2o  5880                   // 50    scaled BL_W2 [10][5]
#define SWM   5936                   // 25    Wm
#define SW2B  5968                   // 5     scaled T_W2
#define STBo  5976                   // 3     T_B
#define SLAM  5980                   // 1     lambda
#define SXo   5984                   // 64*404 = 25856 staged x tile
#define XCHo  (SXo + SPT*XSTR)       // 31840: 64*17 exchange (stride 17: no bank conflicts)
#define SMEM_FLOATS (XCHo + SPT*17)  // 32928 floats = 131712 bytes

typedef unsigned long long ull;

__device__ __forceinline__ ull pk2(float lo, float hi){
    ull r; asm("mov.b64 %0, {%1,%2};" : "=l"(r) : "f"(lo), "f"(hi)); return r;
}
__device__ __forceinline__ float2 upk2(ull v){
    float2 r; asm("mov.b64 {%0,%1}, %2;" : "=f"(r.x), "=f"(r.y) : "l"(v)); return r;
}
__device__ __forceinline__ ull ffma2(ull a, ull b, ull c){
    ull d; asm("fma.rn.f32x2 %0, %1, %2, %3;" : "=l"(d) : "l"(a), "l"(b), "l"(c)); return d;
}
__device__ __forceinline__ ull fmul2(ull a, ull b){
    ull d; asm("mul.rn.f32x2 %0, %1, %2;" : "=l"(d) : "l"(a), "l"(b)); return d;
}
__device__ __forceinline__ ull fadd2(ull a, ull b){
    ull d; asm("add.rn.f32x2 %0, %1, %2;" : "=l"(d) : "l"(a), "l"(b)); return d;
}

// ----------------- preprocessed weights (device globals) -------------------
__device__ float gW1[D2v*D1v];
__device__ float gW2[T1v*T2v];
__device__ float gTW1p[D2v*4];
__device__ float gWm[T2v*T2v];
__device__ float gW2b[T2v];
__device__ float gTB[D3v];
__device__ float gLam;

__global__ void prep_kernel(const float* __restrict__ W1, const float* __restrict__ W2,
                            const float* __restrict__ TW1, const float* __restrict__ TW,
                            const float* __restrict__ TW2, const float* __restrict__ TB,
                            const float* __restrict__ l)
{
    __shared__ float red[512];
    const int tid = threadIdx.x;

    auto nscale = [&](const float* p, int n) -> float {
        float s = 0.f;
        for (int i = tid; i < n; i += 512) s += p[i] * p[i];
        red[tid] = s; __syncthreads();
        for (int o = 256; o > 0; o >>= 1) {
            if (tid < o) red[tid] += red[tid + o];
            __syncthreads();
        }
        float nn = sqrtf(red[0]);
        float sc = (nn > 10.f) ? (10.f / (1e-8f + nn)) : 1.f;
        __syncthreads();
        return sc;
    };

    float s1 = nscale(W1,  D2v*D1v);
    float s2 = nscale(W2,  T1v*T2v);
    float s3 = nscale(TW1, D3v*D2v);
    float s4 = nscale(TW,  T2v*T2v);
    float s5 = nscale(TW2, T2v);

    for (int i = tid; i < D2v*D1v; i += 512) gW1[i] = W1[i] * s1;
    for (int i = tid; i < T1v*T2v; i += 512) gW2[i] = W2[i] * s2;
    for (int i = tid; i < D2v*4;   i += 512) {
        int e = i >> 2, j = i & 3;
        gTW1p[i] = (j < 3) ? TW1[j*D2v + e] * s3 : 0.f;
    }
    for (int i = tid; i < T2v*T2v; i += 512) {
        int r = i / T2v, c = i % T2v;
        gWm[i] = (r == c) ? (1.f / T2v) : TW[i] * s4;
    }
    if (tid < T2v) gW2b[tid] = TW2[tid] * s5;
    if (tid < D3v) gTB[tid]  = TB[tid];
    if (tid == 0) {
        float lv = l[0];
        gLam = fminf(fmaxf(lv, 0.f), 1.f);
    }
}

// ---------------------------- main kernel ----------------------------------
__device__ __forceinline__ void stage_x(const float* __restrict__ gx, float* sm, int tid)
{
    // copy 64 samples * 400 floats (contiguous in global) into padded smem rows
    const float4* src = (const float4*)gx;
    #pragma unroll
    for (int it = 0; it < 40; it++) {
        int i = tid + it * BLK;        // 0..6399
        int s = i / 100;
        int o = i - s * 100;
        unsigned dst = (unsigned)__cvta_generic_to_shared(sm + SXo + s * XSTR + o * 4);
        asm volatile("cp.async.ca.shared.global [%0], [%1], 16;" :: "r"(dst), "l"(src + i));
    }
    asm volatile("cp.async.commit_group;");
}

__device__ __forceinline__ void gemm1(const float* __restrict__ myx,
                                      const ull* __restrict__ w2c, ull* y2)
{
    #pragma unroll
    for (int q = 0; q < 20; q++) {
        const ulonglong2* u = (const ulonglong2*)(myx + q * 20);   // 16B aligned
        ulonglong2 p0 = u[0];   // row0 k0..3
        ulonglong2 p1 = u[1];   // row0 k4..7
        ulonglong2 p2 = u[2];   // row0 k8,9 | row1 k0,1
        ulonglong2 p3 = u[3];   // row1 k2..5
        ulonglong2 p4 = u[4];   // row1 k6..9
        ull a = fmul2(p0.x, w2c[0]);
        ull b = fmul2(p2.y, w2c[0]);
        a = ffma2(p0.y, w2c[1], a);
        b = ffma2(p3.x, w2c[1], b);
        a = ffma2(p1.x, w2c[2], a);
        b = ffma2(p3.y, w2c[2], b);
        a = ffma2(p1.y, w2c[3], a);
        b = ffma2(p4.x, w2c[3], b);
        a = ffma2(p2.x, w2c[4], a);
        b = ffma2(p4.y, w2c[4], b);
        float2 ca = upk2(a), cb = upk2(b);
        y2[q] = pk2(ca.x + ca.y, cb.x + cb.y);
    }
}

__global__ void __launch_bounds__(BLK, 1)
main_kernel(const float* __restrict__ x, const float* __restrict__ Bb,
            float* __restrict__ out)
{
    extern __shared__ float sm[];
    const int tid = threadIdx.x;
    const long long blk_base = (long long)blockIdx.x * (SPT * TPB);

    // prefetch tile 0 while loading weights
    stage_x(x + blk_base * (D1v * T1v), sm, tid);

    for (int i = tid; i < D2v*D1v; i += BLK) sm[SW1 + i] = gW1[i];
    for (int i = tid; i < D2v*T2v; i += BLK) sm[SBo + i] = Bb[i];
    for (int i = tid; i < D2v*4;   i += BLK) sm[STW + i] = gTW1p[i];
    if (tid < 50)                        sm[SW2o + tid]         = gW2[tid];
    else if (tid >= 64  && tid < 89)     sm[SWM  + (tid - 64)]  = gWm[tid - 64];
    else if (tid >= 96  && tid < 101)    sm[SW2B + (tid - 96)]  = gW2b[tid - 96];
    else if (tid >= 104 && tid < 107)    sm[STBo + (tid - 104)] = gTB[tid - 104];
    else if (tid == 112)                 sm[SLAM] = gLam;
    __syncthreads();   // weights visible (x not required yet)

    const int sl = tid / T2v;            // sample slot 0..31 (owns sl and sl+32)
    const int tt = tid - sl * T2v;       // t-column 0..4

    ull w2c[5];
    #pragma unroll
    for (int p = 0; p < 5; p++)
        w2c[p] = pk2(sm[SW2o + (2*p)*T2v + tt], sm[SW2o + (2*p+1)*T2v + tt]);

    for (int tile = 0; tile < TPB; tile++) {
        const long long tbase = blk_base + (long long)tile * SPT;

        asm volatile("cp.async.wait_group 0;" ::: "memory");
        __syncthreads();   // x(tile) visible to all; prior tail finished

        // ---- GEMM1 for both samples ----
        ull y2a[20], y2b[20];
        gemm1(sm + SXo + sl * XSTR,              w2c, y2a);
        gemm1(sm + SXo + (sl + 32) * XSTR,       w2c, y2b);

        __syncthreads();   // x(tile) fully consumed

        if (tile + 1 < TPB)
            stage_x(x + (tbase + SPT) * (D1v * T1v), sm, tid);  // overlap w/ GEMM2

        // ---- GEMM2 + T_W1 projection, both samples share W1-row loads ----
        ull Xa0 = 0ULL, Xa1 = 0ULL, Xb0 = 0ULL, Xb1 = 0ULL;
        const float* bp = sm + SBo + tt;
        #pragma unroll 2
        for (int e = 0; e < D2v; e++) {
            const ulonglong2* w = (const ulonglong2*)(sm + SW1 + e * D1v);
            ulonglong2 w0 = w[0];
            ull aa = fmul2(y2a[0], w0.x), ab = fmul2(y2a[1], w0.y);
            ull ba = fmul2(y2b[0], w0.x), bb = fmul2(y2b[1], w0.y);
            #pragma unroll
            for (int i = 1; i < 10; i++) {
                ulonglong2 wi = w[i];
                aa = ffma2(y2a[2*i],   wi.x, aa);
                ab = ffma2(y2a[2*i+1], wi.y, ab);
                ba = ffma2(y2b[2*i],   wi.x, ba);
                bb = ffma2(y2b[2*i+1], wi.y, bb);
            }
            float bia = bp[e * T2v];
            float2 ca = upk2(fadd2(aa, ab));
            float2 cb = upk2(fadd2(ba, bb));
            float ha = fmaxf(ca.x + ca.y + bia, 0.f);
            float hb = fmaxf(cb.x + cb.y + bia, 0.f);
            ulonglong2 tw = ((const ulonglong2*)(sm + STW))[e];
            ull hda = pk2(ha, ha), hdb = pk2(hb, hb);
            Xa0 = ffma2(tw.x, hda, Xa0);
            Xa1 = ffma2(tw.y, hda, Xa1);
            Xb0 = ffma2(tw.x, hdb, Xb0);
            Xb1 = ffma2(tw.y, hdb, Xb1);
        }

        // exchange X3 columns (stride 17 -> conflict-free tail reads)
        {
            float2 A01 = upk2(Xa0), A2z = upk2(Xa1);
            float2 B01 = upk2(Xb0), B2z = upk2(Xb1);
            float* xca = sm + XCHo + sl * 17;
            float* xcb = sm + XCHo + (sl + 32) * 17;
            xca[0*T2v + tt] = A01.x;
            xca[1*T2v + tt] = A01.y;
            xca[2*T2v + tt] = A2z.x;
            xcb[0*T2v + tt] = B01.x;
            xcb[1*T2v + tt] = B01.y;
            xcb[2*T2v + tt] = B2z.x;
        }
        __syncthreads();   // xch ready

        // ---- per-sample tail (64 threads) ----
        if (tid < SPT) {
            const float* xr = sm + XCHo + tid * 17;
            float X[3][5];
            #pragma unroll
            for (int j = 0; j < 3; j++)
                #pragma unroll
                for (int t = 0; t < 5; t++)
                    X[j][t] = xr[j*5 + t];

            const float lam = sm[SLAM];
            float o3[3];
            #pragma unroll
            for (int j = 0; j < 3; j++) {
                float P[5];
                #pragma unroll
                for (int tp = 0; tp < 5; tp++) {
                    float s = 0.f;
                    #pragma unroll
                    for (int t = 0; t < 5; t++) s += X[j][t] * sm[SWM + t*5 + tp];
                    P[tp] = s;
                }
                float m = P[0];
                #pragma unroll
                for (int tp = 1; tp < 5; tp++) m = fmaxf(m, P[tp]);
                float A[5]; float ssum = 0.f;
                #pragma unroll
                for (int tp = 0; tp < 5; tp++) { A[tp] = __expf(P[tp] - m); ssum += A[tp]; }
                float inv = __fdividef(1.f, ssum);
                float acc = sm[STBo + j];
                #pragma unroll
                for (int t = 0; t < 5; t++) {
                    float Xc = X[j][t] * (lam + (1.f - lam) * A[t] * inv);
                    acc += Xc * sm[SW2B + t];
                }
                o3[j] = acc;
            }
            float m  = fmaxf(o3[0], fmaxf(o3[1], o3[2]));
            float e0 = __expf(o3[0] - m);
            float e1 = __expf(o3[1] - m);
            float e2 = __expf(o3[2] - m);
            float inv = __fdividef(1.f, e0 + e1 + e2);
            long long gs = tbase + tid;
            out[gs*3 + 0] = e0 * inv;
            out[gs*3 + 1] = e1 * inv;
            out[gs*3 + 2] = e2 * inv;
        }
    }
}

// ------------------------------ launch --------------------------------------
extern "C" void kernel_launch(void* const* d_in, const int* in_sizes, int n_in,
                              void* d_out, int out_size)
{
    const float* x   = (const float*)d_in[0];
    const float* W1  = (const float*)d_in[1];
    const float* W2  = (const float*)d_in[2];
    const float* Bb  = (const float*)d_in[3];
    const float* TW1 = (const float*)d_in[4];
    const float* TW  = (const float*)d_in[5];
    const float* TW2 = (const float*)d_in[6];
    const float* TB  = (const float*)d_in[7];
    const float* l   = (const float*)d_in[8];

    const int nsamp = in_sizes[0] / (D1v * T1v);   // 131072

    cudaFuncSetAttribute(main_kernel, cudaFuncAttributeMaxDynamicSharedMemorySize,
                         SMEM_FLOATS * 4);

    prep_kernel<<<1, 512>>>(W1, W2, TW1, TW, TW2, TB, l);

    const int grid = nsamp / (SPT * TPB);          // 512
    main_kernel<<<grid, BLK, SMEM_FLOATS * 4>>>(x, Bb, (float*)d_out);
}

// round 3
// speedup vs baseline: 1.1287x; 1.1287x over previous
#include <cuda_runtime.h>
#include <math.h>

// ---------------------------------------------------------------------------
// m_btabl fused, R3: two-phase.
//  Phase A (memory-bound): y1 = x @ W2a, written to a __device__ scratch in a
//    warp-coalesced ulonglong2 layout ([tile][group][i][lane]).
//  Phase B (fma-bound): GEMM2 + TABL tail with NO x/y1 smem -> 28KB smem,
//    3 blocks/SM (15 warps), 2 sample-columns per thread to amortize W1 LDS.
// ---------------------------------------------------------------------------

#define D1v 40
#define T1v 10
#define D2v 120
#define T2v 5
#define D3v 3

typedef unsigned long long ull;

__device__ __forceinline__ ull pk2(float lo, float hi){
    ull r; asm("mov.b64 %0, {%1,%2};" : "=l"(r) : "f"(lo), "f"(hi)); return r;
}
__device__ __forceinline__ float2 upk2(ull v){
    float2 r; asm("mov.b64 {%0,%1}, %2;" : "=f"(r.x), "=f"(r.y) : "l"(v)); return r;
}
__device__ __forceinline__ ull ffma2(ull a, ull b, ull c){
    ull d; asm("fma.rn.f32x2 %0, %1, %2, %3;" : "=l"(d) : "l"(a), "l"(b), "l"(c)); return d;
}
__device__ __forceinline__ ull fmul2(ull a, ull b){
    ull d; asm("mul.rn.f32x2 %0, %1, %2;" : "=l"(d) : "l"(a), "l"(b)); return d;
}
__device__ __forceinline__ ull fadd2(ull a, ull b){
    ull d; asm("add.rn.f32x2 %0, %1, %2;" : "=l"(d) : "l"(a), "l"(b)); return d;
}

// ----------------- preprocessed weights + scratch ---------------------------
__device__ float gW1[D2v*D1v];
__device__ float gW2[T1v*T2v];
__device__ float gTW1p[D2v*4];
__device__ float gWm[T2v*T2v];
__device__ float gW2b[T2v];
__device__ float gTB[D3v];
__device__ float gLam;

// y1 scratch: 131072 samples * 5 t * 40 d floats = 26.2M floats = 6.55M ull2
__device__ ulonglong2 gY1[131072/64 * 3200];

__global__ void prep_kernel(const float* __restrict__ W1, const float* __restrict__ W2,
                            const float* __restrict__ TW1, const float* __restrict__ TW,
                            const float* __restrict__ TW2, const float* __restrict__ TB,
                            const float* __restrict__ l)
{
    __shared__ float red[512];
    const int tid = threadIdx.x;

    auto nscale = [&](const float* p, int n) -> float {
        float s = 0.f;
        for (int i = tid; i < n; i += 512) s += p[i] * p[i];
        red[tid] = s; __syncthreads();
        for (int o = 256; o > 0; o >>= 1) {
            if (tid < o) red[tid] += red[tid + o];
            __syncthreads();
        }
        float nn = sqrtf(red[0]);
        float sc = (nn > 10.f) ? (10.f / (1e-8f + nn)) : 1.f;
        __syncthreads();
        return sc;
    };

    float s1 = nscale(W1,  D2v*D1v);
    float s2 = nscale(W2,  T1v*T2v);
    float s3 = nscale(TW1, D3v*D2v);
    float s4 = nscale(TW,  T2v*T2v);
    float s5 = nscale(TW2, T2v);

    for (int i = tid; i < D2v*D1v; i += 512) gW1[i] = W1[i] * s1;
    for (int i = tid; i < T1v*T2v; i += 512) gW2[i] = W2[i] * s2;
    for (int i = tid; i < D2v*4;   i += 512) {
        int e = i >> 2, j = i & 3;
        gTW1p[i] = (j < 3) ? TW1[j*D2v + e] * s3 : 0.f;
    }
    for (int i = tid; i < T2v*T2v; i += 512) {
        int r = i / T2v, c = i % T2v;
        gWm[i] = (r == c) ? (1.f / T2v) : TW[i] * s4;
    }
    if (tid < T2v) gW2b[tid] = TW2[tid] * s5;
    if (tid < D3v) gTB[tid]  = TB[tid];
    if (tid == 0) {
        float lv = l[0];
        gLam = fminf(fmaxf(lv, 0.f), 1.f);
    }
}

// ------------------------- phase A: y1 = x @ W2a -----------------------------
// 320 threads, 64 samples/tile. Thread tid -> column c=tid (sample tid/5, t=tid%5).
// Output layout: tile t, group g=c/32, round i (d-pair-pair), lane c%32:
//   gY1[((t*10 + g)*10 + i)*32 + lane]  (ulonglong2 = 4 floats = d 4i..4i+3)

#define ABLK 320
#define XSTR 404

__device__ __forceinline__ void gemm1_col(const float* __restrict__ myx,
                                          const ull* __restrict__ w2c, ull* y2)
{
    #pragma unroll
    for (int q = 0; q < 20; q++) {
        const ulonglong2* u = (const ulonglong2*)(myx + q * 20);
        ulonglong2 p0 = u[0];
        ulonglong2 p1 = u[1];
        ulonglong2 p2 = u[2];
        ulonglong2 p3 = u[3];
        ulonglong2 p4 = u[4];
        ull a = fmul2(p0.x, w2c[0]);
        ull b = fmul2(p2.y, w2c[0]);
        a = ffma2(p0.y, w2c[1], a);
        b = ffma2(p3.x, w2c[1], b);
        a = ffma2(p1.x, w2c[2], a);
        b = ffma2(p3.y, w2c[2], b);
        a = ffma2(p1.y, w2c[3], a);
        b = ffma2(p4.x, w2c[3], b);
        a = ffma2(p2.x, w2c[4], a);
        b = ffma2(p4.y, w2c[4], b);
        float2 ca = upk2(a), cb = upk2(b);
        y2[q] = pk2(ca.x + ca.y, cb.x + cb.y);
    }
}

__global__ void __launch_bounds__(ABLK, 2)
gemm1_kernel(const float* __restrict__ x, int ntiles)
{
    extern __shared__ float sm[];   // 64 * 404 floats = 103424 B
    const int tid = threadIdx.x;
    const int tt  = tid % T2v;

    ull w2c[5];
    #pragma unroll
    for (int p = 0; p < 5; p++)
        w2c[p] = pk2(gW2[(2*p)*T2v + tt], gW2[(2*p+1)*T2v + tt]);

    auto stage = [&](int t){
        const float4* src = (const float4*)(x + (long long)t * (64 * 400));
        #pragma unroll
        for (int it = 0; it < 20; it++) {
            int i = tid + it * ABLK;        // 0..6399
            int s = i / 100;
            int o = i - s * 100;
            unsigned dst = (unsigned)__cvta_generic_to_shared(sm + s * XSTR + o * 4);
            asm volatile("cp.async.ca.shared.global [%0], [%1], 16;" :: "r"(dst), "l"(src + i));
        }
        asm volatile("cp.async.commit_group;");
    };

    int t = blockIdx.x;
    if (t < ntiles) stage(t);
    for (; t < ntiles; t += gridDim.x) {
        asm volatile("cp.async.wait_group 0;" ::: "memory");
        __syncthreads();

        ull y2[20];
        gemm1_col(sm + (tid / T2v) * XSTR, w2c, y2);

        __syncthreads();                 // tile consumed
        int tn = t + gridDim.x;
        if (tn < ntiles) stage(tn);      // overlap next stage with stores

        ulonglong2* dst = gY1 + ((t * 10 + (tid >> 5)) * 10) * 32 + (tid & 31);
        #pragma unroll
        for (int i = 0; i < 10; i++)
            dst[i * 32] = make_ulonglong2(y2[2*i], y2[2*i+1]);
    }
}

// ------------------------- phase B: GEMM2 + TABL tail ------------------------
#define BBLK 160
// smem layout (floats)
#define BW1   0        // 4800
#define BBo   4800     // 600
#define BTW   5400     // 480
#define BWM   5880     // 25
#define BW2B  5905     // 5
#define BTB   5910     // 3
#define BLAM  5913     // 1
#define BXCH  5916     // 64*17 = 1088
#define BSM   (BXCH + 64*17)

__global__ void __launch_bounds__(BBLK, 3)
main_kernel(const float* __restrict__ Bb, float* __restrict__ out, int ntiles)
{
    __shared__ float sm[BSM];
    const int tid = threadIdx.x;

    for (int i = tid; i < D2v*D1v; i += BBLK) sm[BW1 + i] = gW1[i];
    for (int i = tid; i < D2v*T2v; i += BBLK) sm[BBo + i] = Bb[i];
    for (int i = tid; i < D2v*4;   i += BBLK) sm[BTW + i] = gTW1p[i];
    if (tid < 25)                     sm[BWM  + tid]        = gWm[tid];
    else if (tid >= 32 && tid < 37)   sm[BW2B + (tid - 32)] = gW2b[tid - 32];
    else if (tid >= 40 && tid < 43)   sm[BTB  + (tid - 40)] = gTB[tid - 40];
    else if (tid == 48)               sm[BLAM] = gLam;
    __syncthreads();

    const int sl = tid / T2v;        // 0..31
    const int tt = tid - sl * T2v;   // 0..4
    const int w  = tid >> 5;         // warp 0..4 = y1 group
    const int la = tid & 31;

    for (int t = blockIdx.x; t < ntiles; t += gridDim.x) {
        // ---- load both y1 columns (coalesced LDG.128) ----
        const ulonglong2* pa = gY1 + ((t * 10 + w) * 10) * 32 + la;
        const ulonglong2* pb = pa + 5 * 10 * 32;       // samples +32 -> groups 5..9
        ull y2a[20], y2b[20];
        #pragma unroll
        for (int i = 0; i < 10; i++) {
            ulonglong2 va = __ldg(pa + i * 32);
            ulonglong2 vb = __ldg(pb + i * 32);
            y2a[2*i] = va.x; y2a[2*i+1] = va.y;
            y2b[2*i] = vb.x; y2b[2*i+1] = vb.y;
        }

        // ---- GEMM2 + T_W1 projection (shared W1-row loads) ----
        ull Xa0 = 0ULL, Xa1 = 0ULL, Xb0 = 0ULL, Xb1 = 0ULL;
        const float* bp = sm + BBo + tt;
        #pragma unroll 2
        for (int e = 0; e < D2v; e++) {
            const ulonglong2* wv = (const ulonglong2*)(sm + BW1 + e * D1v);
            ulonglong2 w0 = wv[0];
            ull aa = fmul2(y2a[0], w0.x), ab = fmul2(y2a[1], w0.y);
            ull ba = fmul2(y2b[0], w0.x), bb = fmul2(y2b[1], w0.y);
            #pragma unroll
            for (int i = 1; i < 10; i++) {
                ulonglong2 wi = wv[i];
                aa = ffma2(y2a[2*i],   wi.x, aa);
                ab = ffma2(y2a[2*i+1], wi.y, ab);
                ba = ffma2(y2b[2*i],   wi.x, ba);
                bb = ffma2(y2b[2*i+1], wi.y, bb);
            }
            float bia = bp[e * T2v];
            float2 ca = upk2(fadd2(aa, ab));
            float2 cb = upk2(fadd2(ba, bb));
            float ha = fmaxf(ca.x + ca.y + bia, 0.f);
            float hb = fmaxf(cb.x + cb.y + bia, 0.f);
            ulonglong2 tw = ((const ulonglong2*)(sm + BTW))[e];
            ull hda = pk2(ha, ha), hdb = pk2(hb, hb);
            Xa0 = ffma2(tw.x, hda, Xa0);
            Xa1 = ffma2(tw.y, hda, Xa1);
            Xb0 = ffma2(tw.x, hdb, Xb0);
            Xb1 = ffma2(tw.y, hdb, Xb1);
        }

        // ---- exchange X3 ----
        {
            float2 A01 = upk2(Xa0), A2z = upk2(Xa1);
            float2 B01 = upk2(Xb0), B2z = upk2(Xb1);
            float* xca = sm + BXCH + sl * 17;
            float* xcb = sm + BXCH + (sl + 32) * 17;
            xca[0*T2v + tt] = A01.x;
            xca[1*T2v + tt] = A01.y;
            xca[2*T2v + tt] = A2z.x;
            xcb[0*T2v + tt] = B01.x;
            xcb[1*T2v + tt] = B01.y;
            xcb[2*T2v + tt] = B2z.x;
        }
        __syncthreads();

        // ---- per-sample tail (64 threads) ----
        if (tid < 64) {
            const float* xr = sm + BXCH + tid * 17;
            float X[3][5];
            #pragma unroll
            for (int j = 0; j < 3; j++)
                #pragma unroll
                for (int tq = 0; tq < 5; tq++)
                    X[j][tq] = xr[j*5 + tq];

            const float lam = sm[BLAM];
            float o3[3];
            #pragma unroll
            for (int j = 0; j < 3; j++) {
                float P[5];
                #pragma unroll
                for (int tp = 0; tp < 5; tp++) {
                    float s = 0.f;
                    #pragma unroll
                    for (int tq = 0; tq < 5; tq++) s += X[j][tq] * sm[BWM + tq*5 + tp];
                    P[tp] = s;
                }
                float m = P[0];
                #pragma unroll
                for (int tp = 1; tp < 5; tp++) m = fmaxf(m, P[tp]);
                float A[5]; float ssum = 0.f;
                #pragma unroll
                for (int tp = 0; tp < 5; tp++) { A[tp] = __expf(P[tp] - m); ssum += A[tp]; }
                float inv = __fdividef(1.f, ssum);
                float acc = sm[BTB + j];
                #pragma unroll
                for (int tq = 0; tq < 5; tq++) {
                    float Xc = X[j][tq] * (lam + (1.f - lam) * A[tq] * inv);
                    acc += Xc * sm[BW2B + tq];
                }
                o3[j] = acc;
            }
            float m  = fmaxf(o3[0], fmaxf(o3[1], o3[2]));
            float e0 = __expf(o3[0] - m);
            float e1 = __expf(o3[1] - m);
            float e2 = __expf(o3[2] - m);
            float inv = __fdividef(1.f, e0 + e1 + e2);
            long long gs = (long long)t * 64 + tid;
            out[gs*3 + 0] = e0 * inv;
            out[gs*3 + 1] = e1 * inv;
            out[gs*3 + 2] = e2 * inv;
        }
        __syncthreads();   // xch reusable next tile
    }
}

// ------------------------------ launch --------------------------------------
extern "C" void kernel_launch(void* const* d_in, const int* in_sizes, int n_in,
                              void* d_out, int out_size)
{
    const float* x   = (const float*)d_in[0];
    const float* W1  = (const float*)d_in[1];
    const float* W2  = (const float*)d_in[2];
    const float* Bb  = (const float*)d_in[3];
    const float* TW1 = (const float*)d_in[4];
    const float* TW  = (const float*)d_in[5];
    const float* TW2 = (const float*)d_in[6];
    const float* TB  = (const float*)d_in[7];
    const float* l   = (const float*)d_in[8];

    const int nsamp  = in_sizes[0] / (D1v * T1v);   // 131072
    const int ntiles = nsamp / 64;                  // 2048

    cudaFuncSetAttribute(gemm1_kernel, cudaFuncAttributeMaxDynamicSharedMemorySize,
                         64 * XSTR * 4);

    prep_kernel<<<1, 512>>>(W1, W2, TW1, TW, TW2, TB, l);

    int gridA = 296;  if (gridA > ntiles) gridA = ntiles;
    gemm1_kernel<<<gridA, ABLK, 64 * XSTR * 4>>>(x, ntiles);

    int gridB = 444;  if (gridB > ntiles) gridB = ntiles;
    main_kernel<<<gridB, BBLK>>>(Bb, (float*)d_out, ntiles);
}

// round 4
// speedup vs baseline: 1.3375x; 1.1850x over previous
#include <cuda_runtime.h>
#include <math.h>

// ---------------------------------------------------------------------------
// m_btabl, R4: single fused kernel.
//  * in-kernel max_norm (5 warps = 5 matrices, shuffle reductions)
//  * GEMM1 straight from global x (5 lanes/sample read same addrs -> L1 dedup)
//  * GEMM2: 2 sample-cols/thread, W1 rows broadcast from smem, packed f32x2
//  * tiny smem (28KB) -> 3 blocks/SM, 15 warps
// ---------------------------------------------------------------------------

#define D1v 40
#define T1v 10
#define D2v 120
#define T2v 5
#define D3v 3

#define BLK 160          // 5 warps: 32 sample-slots x 5 t-cols, 2 samples/thread

// smem layout (float offsets)
#define SW1   0                      // 4800  scaled BL_W1 [120][40]
#define SBo   4800                   // 600   BL_B [120][5]
#define STW   5400                   // 480   scaled T_W1 transposed+padded [120][4]
#define SW2o  5880                   // 50    scaled BL_W2 [10][5]
#define SWM   5936                   // 25    Wm
#define SW2B  5961                   // 5
#define STBo  5966                   // 3
#define SLAM  5969                   // 1
#define SSC   5970                   // 6 scales
#define SXCH  5984                   // 64*17 = 1088 exchange
#define SMF   (SXCH + 64*17)         // 7072 floats = 28288 B

typedef unsigned long long ull;

__device__ __forceinline__ ull pk2(float lo, float hi){
    ull r; asm("mov.b64 %0, {%1,%2};" : "=l"(r) : "f"(lo), "f"(hi)); return r;
}
__device__ __forceinline__ float2 upk2(ull v){
    float2 r; asm("mov.b64 {%0,%1}, %2;" : "=f"(r.x), "=f"(r.y) : "l"(v)); return r;
}
__device__ __forceinline__ ull ffma2(ull a, ull b, ull c){
    ull d; asm("fma.rn.f32x2 %0, %1, %2, %3;" : "=l"(d) : "l"(a), "l"(b), "l"(c)); return d;
}
__device__ __forceinline__ ull fmul2(ull a, ull b){
    ull d; asm("mul.rn.f32x2 %0, %1, %2;" : "=l"(d) : "l"(a), "l"(b)); return d;
}
__device__ __forceinline__ ull fadd2(ull a, ull b){
    ull d; asm("add.rn.f32x2 %0, %1, %2;" : "=l"(d) : "l"(a), "l"(b)); return d;
}

// GEMM1 for one column: y1[:, tt] as 20 packed pairs, read from ptr (global or smem)
__device__ __forceinline__ void gemm1_col(const float* __restrict__ myx,
                                          const ull* __restrict__ w2c, ull* y2)
{
    #pragma unroll
    for (int q = 0; q < 20; q++) {
        const ulonglong2* u = (const ulonglong2*)(myx + q * 20);   // 80B aligned
        ulonglong2 p0 = u[0];
        ulonglong2 p1 = u[1];
        ulonglong2 p2 = u[2];
        ulonglong2 p3 = u[3];
        ulonglong2 p4 = u[4];
        ull a = fmul2(p0.x, w2c[0]);
        ull b = fmul2(p2.y, w2c[0]);
        a = ffma2(p0.y, w2c[1], a);
        b = ffma2(p3.x, w2c[1], b);
        a = ffma2(p1.x, w2c[2], a);
        b = ffma2(p3.y, w2c[2], b);
        a = ffma2(p1.y, w2c[3], a);
        b = ffma2(p4.x, w2c[3], b);
        a = ffma2(p2.x, w2c[4], a);
        b = ffma2(p4.y, w2c[4], b);
        float2 ca = upk2(a), cb = upk2(b);
        y2[q] = pk2(ca.x + ca.y, cb.x + cb.y);
    }
}

__global__ void __launch_bounds__(BLK, 3)
fused_kernel(const float* __restrict__ x,   const float* __restrict__ W1,
             const float* __restrict__ W2,  const float* __restrict__ Bb,
             const float* __restrict__ TW1, const float* __restrict__ TW,
             const float* __restrict__ TW2, const float* __restrict__ TB,
             const float* __restrict__ l,   float* __restrict__ out, int ntiles)
{
    __shared__ float sm[SMF];
    const int tid  = threadIdx.x;
    const int wid  = tid >> 5;
    const int lane = tid & 31;

    // ---- in-kernel max_norm scales: warp w handles matrix w ----
    {
        const float* mp; int n;
        switch (wid) {
            case 0: mp = W1;  n = D2v*D1v; break;
            case 1: mp = TW1; n = D3v*D2v; break;
            case 2: mp = W2;  n = T1v*T2v; break;
            case 3: mp = TW;  n = T2v*T2v; break;
            default: mp = TW2; n = T2v;    break;
        }
        float s = 0.f;
        for (int i = lane; i < n; i += 32) { float v = mp[i]; s += v * v; }
        #pragma unroll
        for (int o = 16; o > 0; o >>= 1) s += __shfl_xor_sync(0xffffffffu, s, o);
        if (lane == 0) {
            float nn = sqrtf(s);
            sm[SSC + wid] = (nn > 10.f) ? (10.f / (1e-8f + nn)) : 1.f;
        }
    }
    __syncthreads();
    const float s1 = sm[SSC+0], s3 = sm[SSC+1], s2 = sm[SSC+2],
                s4 = sm[SSC+3], s5 = sm[SSC+4];

    // ---- scaled weights -> smem ----
    for (int i = tid; i < D2v*D1v; i += BLK) sm[SW1 + i] = W1[i] * s1;
    for (int i = tid; i < D2v*T2v; i += BLK) sm[SBo + i] = Bb[i];
    for (int i = tid; i < D2v*4;   i += BLK) {
        int e = i >> 2, j = i & 3;
        sm[STW + i] = (j < 3) ? TW1[j*D2v + e] * s3 : 0.f;
    }
    if (tid < 50)                     sm[SW2o + tid] = W2[tid] * s2;
    else if (tid >= 64 && tid < 89) {
        int i = tid - 64, r = i / 5, c = i - r * 5;
        sm[SWM + i] = (r == c) ? (1.f / T2v) : TW[i] * s4;
    }
    else if (tid >= 96  && tid < 101) sm[SW2B + (tid - 96)]  = TW2[tid - 96] * s5;
    else if (tid >= 104 && tid < 107) sm[STBo + (tid - 104)] = TB[tid - 104];
    else if (tid == 112) {
        float lv = l[0];
        sm[SLAM] = fminf(fmaxf(lv, 0.f), 1.f);
    }
    __syncthreads();

    const int sl = tid / T2v;        // 0..31 (owns samples sl, sl+32 of tile)
    const int tt = tid - sl * T2v;   // 0..4

    ull w2c[5];
    #pragma unroll
    for (int p = 0; p < 5; p++)
        w2c[p] = pk2(sm[SW2o + (2*p)*T2v + tt], sm[SW2o + (2*p+1)*T2v + tt]);

    for (int t = blockIdx.x; t < ntiles; t += gridDim.x) {
        const long long base = (long long)t * 64;

        // ---- GEMM1 directly from global x ----
        ull y2a[20], y2b[20];
        gemm1_col(x + (base + sl)      * (D1v*T1v), w2c, y2a);
        gemm1_col(x + (base + sl + 32) * (D1v*T1v), w2c, y2b);

        // ---- GEMM2 + T_W1 projection (shared broadcast W1 loads) ----
        ull Xa0 = 0ULL, Xa1 = 0ULL, Xb0 = 0ULL, Xb1 = 0ULL;
        const float* bp = sm + SBo + tt;
        #pragma unroll 2
        for (int e = 0; e < D2v; e++) {
            const ulonglong2* wv = (const ulonglong2*)(sm + SW1 + e * D1v);
            ulonglong2 w0 = wv[0];
            ull aa = fmul2(y2a[0], w0.x), ab = fmul2(y2a[1], w0.y);
            ull ba = fmul2(y2b[0], w0.x), bb = fmul2(y2b[1], w0.y);
            #pragma unroll
            for (int i = 1; i < 10; i++) {
                ulonglong2 wi = wv[i];
                aa = ffma2(y2a[2*i],   wi.x, aa);
                ab = ffma2(y2a[2*i+1], wi.y, ab);
                ba = ffma2(y2b[2*i],   wi.x, ba);
                bb = ffma2(y2b[2*i+1], wi.y, bb);
            }
            float bia = bp[e * T2v];
            float2 ca = upk2(fadd2(aa, ab));
            float2 cb = upk2(fadd2(ba, bb));
            float ha = fmaxf(ca.x + ca.y + bia, 0.f);
            float hb = fmaxf(cb.x + cb.y + bia, 0.f);
            ulonglong2 tw = ((const ulonglong2*)(sm + STW))[e];
            ull hda = pk2(ha, ha), hdb = pk2(hb, hb);
            Xa0 = ffma2(tw.x, hda, Xa0);
            Xa1 = ffma2(tw.y, hda, Xa1);
            Xb0 = ffma2(tw.x, hdb, Xb0);
            Xb1 = ffma2(tw.y, hdb, Xb1);
        }

        // ---- exchange X3 (stride 17, conflict-free) ----
        {
            float2 A01 = upk2(Xa0), A2z = upk2(Xa1);
            float2 B01 = upk2(Xb0), B2z = upk2(Xb1);
            float* xca = sm + SXCH + sl * 17;
            float* xcb = sm + SXCH + (sl + 32) * 17;
            xca[0*T2v + tt] = A01.x;
            xca[1*T2v + tt] = A01.y;
            xca[2*T2v + tt] = A2z.x;
            xcb[0*T2v + tt] = B01.x;
            xcb[1*T2v + tt] = B01.y;
            xcb[2*T2v + tt] = B2z.x;
        }
        __syncthreads();

        // ---- per-sample tail (64 threads) ----
        if (tid < 64) {
            const float* xr = sm + SXCH + tid * 17;
            float X[3][5];
            #pragma unroll
            for (int j = 0; j < 3; j++)
                #pragma unroll
                for (int tq = 0; tq < 5; tq++)
                    X[j][tq] = xr[j*5 + tq];

            const float lam = sm[SLAM];
            float o3[3];
            #pragma unroll
            for (int j = 0; j < 3; j++) {
                float P[5];
                #pragma unroll
                for (int tp = 0; tp < 5; tp++) {
                    float s = 0.f;
                    #pragma unroll
                    for (int tq = 0; tq < 5; tq++) s += X[j][tq] * sm[SWM + tq*5 + tp];
                    P[tp] = s;
                }
                float m = P[0];
                #pragma unroll
                for (int tp = 1; tp < 5; tp++) m = fmaxf(m, P[tp]);
                float A[5]; float ssum = 0.f;
                #pragma unroll
                for (int tp = 0; tp < 5; tp++) { A[tp] = __expf(P[tp] - m); ssum += A[tp]; }
                float inv = __fdividef(1.f, ssum);
                float acc = sm[STBo + j];
                #pragma unroll
                for (int tq = 0; tq < 5; tq++) {
                    float Xc = X[j][tq] * (lam + (1.f - lam) * A[tq] * inv);
                    acc += Xc * sm[SW2B + tq];
                }
                o3[j] = acc;
            }
            float m  = fmaxf(o3[0], fmaxf(o3[1], o3[2]));
            float e0 = __expf(o3[0] - m);
            float e1 = __expf(o3[1] - m);
            float e2 = __expf(o3[2] - m);
            float inv = __fdividef(1.f, e0 + e1 + e2);
            long long gs = base + tid;
            out[gs*3 + 0] = e0 * inv;
            out[gs*3 + 1] = e1 * inv;
            out[gs*3 + 2] = e2 * inv;
        }
        __syncthreads();   // exchange reusable
    }
}

// ------------------------------ launch --------------------------------------
extern "C" void kernel_launch(void* const* d_in, const int* in_sizes, int n_in,
                              void* d_out, int out_size)
{
    const float* x   = (const float*)d_in[0];
    const float* W1  = (const float*)d_in[1];
    const float* W2  = (const float*)d_in[2];
    const float* Bb  = (const float*)d_in[3];
    const float* TW1 = (const float*)d_in[4];
    const float* TW  = (const float*)d_in[5];
    const float* TW2 = (const float*)d_in[6];
    const float* TB  = (const float*)d_in[7];
    const float* l   = (const float*)d_in[8];

    const int nsamp  = in_sizes[0] / (D1v * T1v);   // 131072
    const int ntiles = nsamp / 64;                  // 2048

    int grid = 456;                                 // 3 per SM on 152 SMs
    if (grid > ntiles) grid = ntiles;

    fused_kernel<<<grid, BLK>>>(x, W1, W2, Bb, TW1, TW, TW2, TB, l,
                                (float*)d_out, ntiles);
}